// round 5
// baseline (speedup 1.0000x reference)
#include <cuda_runtime.h>
#include <math.h>

#define NROWS   131072          // 64*2048
#define DIN     384
#define DHID    256
#define DLAT    128
#define KC      256
#define TM      64
#define NTHREADS 256
#define NBLOCKS (NROWS / TM)    // 2048

// shared memory layout (floats):
//  [0,16384)      sH (64x256)  -- sZ (64x128) aliases [0,8192) after GEMM2
//  [16384,20736)  sW buf0 (4352)
//  [20736,25088)  sW buf1 (4352)   -- GEMM3 cb^T tile (32x260=8320) spans both buffers
//  [25088,25344)  sCn (256)
//  [25344,25360)  sLoss (8 doubles)
#define SW_BASE   16384
#define SW_BUFSZ  4352
#define CN_BASE   25088
#define LOSS_BASE 25344
#define SMEM_FLOATS 25360
#define SMEM_BYTES  (SMEM_FLOATS * 4)

__device__ double       g_partials[NBLOCKS];
__device__ unsigned int g_ticket = 0;

typedef unsigned long long u64;

__device__ __forceinline__ float warp_sum(float v) {
#pragma unroll
    for (int o = 16; o > 0; o >>= 1) v += __shfl_xor_sync(0xffffffffu, v, o);
    return v;
}
__device__ __forceinline__ u64 dup2(float x) {
    u64 r; asm("mov.b64 %0, {%1, %1};" : "=l"(r) : "f"(x)); return r;
}
__device__ __forceinline__ u64 fma2(u64 a, u64 b, u64 c) {
    u64 d; asm("fma.rn.f32x2 %0, %1, %2, %3;" : "=l"(d) : "l"(a), "l"(b), "l"(c)); return d;
}
__device__ __forceinline__ void unpack2(u64 p, float& lo, float& hi) {
    asm("mov.b64 {%0, %1}, %2;" : "=f"(lo), "=f"(hi) : "l"(p));
}
__device__ __forceinline__ void cp16(unsigned dst, const void* src) {
    asm volatile("cp.async.cg.shared.global [%0], [%1], 16;" :: "r"(dst), "l"(src));
}
__device__ __forceinline__ void cp_commit() { asm volatile("cp.async.commit_group;"); }
__device__ __forceinline__ void cp_wait0()  { asm volatile("cp.async.wait_group 0;"); }

extern "C" __global__ void __launch_bounds__(NTHREADS, 2)
vq_fused_kernel(const float* __restrict__ emb,
                const float* __restrict__ W1, const float* __restrict__ b1,
                const float* __restrict__ g1, const float* __restrict__ be1,
                const float* __restrict__ W2, const float* __restrict__ b2,
                const float* __restrict__ g2, const float* __restrict__ be2,
                const float* __restrict__ cb,
                float* __restrict__ outZ,
                float* __restrict__ outIdx,
                float* __restrict__ outLoss,
                int writeAux)
{
    extern __shared__ float sm[];
    float*  sH   = sm;                       // 64x256
    float*  sZ   = sm;                       // 64x128, aliases sH after GEMM2
    float*  sCn  = sm + CN_BASE;
    double* sLoss = (double*)(sm + LOSS_BASE);

    const int tid  = threadIdx.x;
    const int wid  = tid >> 5;               // 0..7
    const int lane = tid & 31;
    const int rb   = wid * 8;                // this warp's 8 rows
    const int r0   = blockIdx.x * TM;
    const int cA0  = lane * 4;               // cols [4l, 4l+3]
    const int cB0  = 128 + lane * 4;         // cols [128+4l, ...]

    const unsigned swb[2] = { (unsigned)__cvta_generic_to_shared(sm + SW_BASE),
                              (unsigned)__cvta_generic_to_shared(sm + SW_BASE + SW_BUFSZ) };

    // ---- codebook squared norms (one code per thread) ----
    {
        const float4* cv4 = (const float4*)cb + (size_t)tid * (DLAT / 4);
        float s = 0.f;
#pragma unroll
        for (int q = 0; q < 32; q++) {
            float4 v = cv4[q];
            s += v.x * v.x + v.y * v.y + v.z * v.z + v.w * v.w;
        }
        sCn[tid] = s;
    }

    // =================== GEMM1: [64,384] @ W1[384,256], k-tiles of 16, cp.async db ===================
    u64 acc1[8][4];
#pragma unroll
    for (int i = 0; i < 8; i++)
#pragma unroll
        for (int p = 0; p < 4; p++) acc1[i][p] = 0ULL;

    // prefetch tile 0: 16x256 floats = 1024 float4; 4 per thread
    {
        const float4* src = (const float4*)W1;   // tile 0 starts at k=0
#pragma unroll
        for (int q = 0; q < 4; q++) cp16(swb[0] + (tid + q * 256) * 16, src + tid + q * 256);
        cp_commit();
    }
    const float* xbase = emb + (size_t)(r0 + rb) * DIN;   // row rb of this block

    for (int t = 0; t < 24; t++) {
        cp_wait0();
        __syncthreads();
        if (t + 1 < 24) {
            const float4* src = (const float4*)(W1 + (t + 1) * 16 * 256);
            unsigned dst = swb[(t + 1) & 1];
#pragma unroll
            for (int q = 0; q < 4; q++) cp16(dst + (tid + q * 256) * 16, src + tid + q * 256);
            cp_commit();
        }
        const float* buf = sm + SW_BASE + (t & 1) * SW_BUFSZ;
#pragma unroll
        for (int kg = 0; kg < 4; kg++) {
            ulonglong2 wA[4], wB[4];
#pragma unroll
            for (int kq = 0; kq < 4; kq++) {
                const int kk = kg * 4 + kq;
                wA[kq] = ((const ulonglong2*)buf)[kk * 64 + lane];
                wB[kq] = ((const ulonglong2*)buf)[kk * 64 + 32 + lane];
            }
#pragma unroll
            for (int i = 0; i < 8; i++) {
                float4 xv = __ldg((const float4*)(xbase + i * DIN + t * 16 + kg * 4));
#pragma unroll
                for (int kq = 0; kq < 4; kq++) {
                    float xs = (kq == 0) ? xv.x : (kq == 1) ? xv.y : (kq == 2) ? xv.z : xv.w;
                    u64 xx = dup2(xs);
                    acc1[i][0] = fma2(xx, wA[kq].x, acc1[i][0]);
                    acc1[i][1] = fma2(xx, wA[kq].y, acc1[i][1]);
                    acc1[i][2] = fma2(xx, wB[kq].x, acc1[i][2]);
                    acc1[i][3] = fma2(xx, wB[kq].y, acc1[i][3]);
                }
            }
        }
    }

    // prefetch W2 tile 0 (overlaps LN1+GELU); all warps past t=23 barrier -> buf0 free
    {
        const float4* src = (const float4*)W2;   // 16x128 = 512 float4; 2 per thread
#pragma unroll
        for (int q = 0; q < 2; q++) cp16(swb[0] + (tid + q * 256) * 16, src + tid + q * 256);
        cp_commit();
    }

    // =================== bias + LayerNorm1 + exact GELU -> sH ===================
    {
        float4 bA = __ldg((const float4*)(b1 + cA0)),  bB = __ldg((const float4*)(b1 + cB0));
        float4 gA = __ldg((const float4*)(g1 + cA0)),  gB = __ldg((const float4*)(g1 + cB0));
        float4 eA = __ldg((const float4*)(be1 + cA0)), eB = __ldg((const float4*)(be1 + cB0));
        float b1v[8] = {bA.x,bA.y,bA.z,bA.w,bB.x,bB.y,bB.z,bB.w};
        float g1v[8] = {gA.x,gA.y,gA.z,gA.w,gB.x,gB.y,gB.z,gB.w};
        float e1v[8] = {eA.x,eA.y,eA.z,eA.w,eB.x,eB.y,eB.z,eB.w};
#pragma unroll
        for (int i = 0; i < 8; i++) {
            float v[8], s = 0.f;
#pragma unroll
            for (int p = 0; p < 4; p++) unpack2(acc1[i][p], v[2*p], v[2*p+1]);
#pragma unroll
            for (int j = 0; j < 8; j++) { v[j] = v[j] + b1v[j]; s += v[j]; }
            s = warp_sum(s);
            float mean = s * (1.f / 256.f);
            float ss = 0.f;
#pragma unroll
            for (int j = 0; j < 8; j++) { float d = v[j] - mean; ss += d * d; }
            ss = warp_sum(ss);
            float rstd = rsqrtf(ss * (1.f / 256.f) + 1e-5f);
            float h[8];
#pragma unroll
            for (int j = 0; j < 8; j++) {
                float tt = (v[j] - mean) * rstd * g1v[j] + e1v[j];
                h[j] = 0.5f * tt * (1.f + erff(tt * 0.70710678118654752f));
            }
            *(float4*)&sH[(rb + i) * 256 + cA0] = make_float4(h[0], h[1], h[2], h[3]);
            *(float4*)&sH[(rb + i) * 256 + cB0] = make_float4(h[4], h[5], h[6], h[7]);
        }
    }
    __syncthreads();   // H visible to all warps

    // =================== GEMM2: [64,256] @ W2[256,128], k-tiles of 16, cp.async db ===================
    u64 acc2[8][2];
#pragma unroll
    for (int i = 0; i < 8; i++) { acc2[i][0] = 0ULL; acc2[i][1] = 0ULL; }

    for (int t = 0; t < 16; t++) {
        cp_wait0();
        __syncthreads();
        if (t + 1 < 16) {
            const float4* src = (const float4*)(W2 + (t + 1) * 16 * 128);
            unsigned dst = swb[(t + 1) & 1];
#pragma unroll
            for (int q = 0; q < 2; q++) cp16(dst + (tid + q * 256) * 16, src + tid + q * 256);
            cp_commit();
        }
        const float* buf = sm + SW_BASE + (t & 1) * SW_BUFSZ;
#pragma unroll
        for (int kg = 0; kg < 4; kg++) {
            ulonglong2 wv[4];
#pragma unroll
            for (int kq = 0; kq < 4; kq++)
                wv[kq] = ((const ulonglong2*)buf)[(kg * 4 + kq) * 32 + lane];
#pragma unroll
            for (int i = 0; i < 8; i++) {
                float4 xv = *(const float4*)&sH[(rb + i) * 256 + t * 16 + kg * 4];
#pragma unroll
                for (int kq = 0; kq < 4; kq++) {
                    float xs = (kq == 0) ? xv.x : (kq == 1) ? xv.y : (kq == 2) ? xv.z : xv.w;
                    u64 xx = dup2(xs);
                    acc2[i][0] = fma2(xx, wv[kq].x, acc2[i][0]);
                    acc2[i][1] = fma2(xx, wv[kq].y, acc2[i][1]);
                }
            }
        }
    }
    __syncthreads();   // all H reads done before z overwrites sH[0:8192)

    // =================== bias + LayerNorm2 -> z (SMEM, aliases sH), ||z||^2 ===================
    float zsq[8];
    {
        float4 b2v = __ldg((const float4*)(b2 + cA0));
        float4 g2v = __ldg((const float4*)(g2 + cA0));
        float4 e2v = __ldg((const float4*)(be2 + cA0));
#pragma unroll
        for (int i = 0; i < 8; i++) {
            float a0, a1, a2, a3;
            unpack2(acc2[i][0], a0, a1);
            unpack2(acc2[i][1], a2, a3);
            float v0 = a0 + b2v.x, v1 = a1 + b2v.y;
            float v2 = a2 + b2v.z, v3 = a3 + b2v.w;
            float s = warp_sum(v0 + v1 + v2 + v3);
            float mean = s * (1.f / 128.f);
            float d0 = v0 - mean, d1 = v1 - mean, d2 = v2 - mean, d3 = v3 - mean;
            float ss = warp_sum(d0 * d0 + d1 * d1 + d2 * d2 + d3 * d3);
            float rstd = rsqrtf(ss * (1.f / 128.f) + 1e-5f);
            float z0 = d0 * rstd * g2v.x + e2v.x;
            float z1 = d1 * rstd * g2v.y + e2v.y;
            float z2 = d2 * rstd * g2v.z + e2v.z;
            float z3 = d3 * rstd * g2v.w + e2v.w;
            zsq[i] = warp_sum(z0 * z0 + z1 * z1 + z2 * z2 + z3 * z3);
            *(float4*)&sZ[(rb + i) * 128 + cA0] = make_float4(z0, z1, z2, z3);
        }
    }
    __syncthreads();   // z visible

    // =================== distance GEMM: z[64,128] . cb[256,128]^T, k-tiles of 32 ===================
    u64 acc3[8][4];
#pragma unroll
    for (int i = 0; i < 8; i++)
#pragma unroll
        for (int p = 0; p < 4; p++) acc3[i][p] = 0ULL;

    float* sWc = sm + SW_BASE;   // 32x260 transposed cb tile (spans both buffers)

    for (int kt = 0; kt < DLAT; kt += 32) {
        // stage transposed codebook tile: sWc[kk*260 + code] = cb[code][kt+kk]
        {
            const float4* cv4 = (const float4*)cb + (size_t)tid * 32 + (kt >> 2);
#pragma unroll
            for (int q = 0; q < 8; q++) {
                float4 v = cv4[q];
                int kk = q * 4;
                sWc[(kk + 0) * 260 + tid] = v.x;
                sWc[(kk + 1) * 260 + tid] = v.y;
                sWc[(kk + 2) * 260 + tid] = v.z;
                sWc[(kk + 3) * 260 + tid] = v.w;
            }
        }
        __syncthreads();
#pragma unroll
        for (int kg = 0; kg < 8; kg++) {
            ulonglong2 cA[2], cB[2];   // 2 kq at a time to bound regs
#pragma unroll
            for (int kh = 0; kh < 2; kh++) {
#pragma unroll
                for (int kq = 0; kq < 2; kq++) {
                    const int kk = kg * 4 + kh * 2 + kq;
                    cA[kq] = *(const ulonglong2*)&sWc[kk * 260 + cA0];
                    cB[kq] = *(const ulonglong2*)&sWc[kk * 260 + cB0];
                }
#pragma unroll
                for (int i = 0; i < 8; i++) {
                    float2 zp = *(const float2*)&sZ[(rb + i) * 128 + kt + kg * 4 + kh * 2];
#pragma unroll
                    for (int kq = 0; kq < 2; kq++) {
                        u64 zz = dup2(kq == 0 ? zp.x : zp.y);
                        acc3[i][0] = fma2(zz, cA[kq].x, acc3[i][0]);
                        acc3[i][1] = fma2(zz, cA[kq].y, acc3[i][1]);
                        acc3[i][2] = fma2(zz, cB[kq].x, acc3[i][2]);
                        acc3[i][3] = fma2(zz, cB[kq].y, acc3[i][3]);
                    }
                }
            }
        }
        __syncthreads();   // before next tile's STS overwrite
    }

    // ---- codebook norms for this thread's 8 codes ----
    float cnA[4], cnB[4];
#pragma unroll
    for (int q = 0; q < 4; q++) { cnA[q] = sCn[cA0 + q]; cnB[q] = sCn[cB0 + q]; }

    // =================== argmin + outputs + loss ===================
    double lsum = 0.0;
#pragma unroll
    for (int i = 0; i < 8; i++) {
        float dot[8];
#pragma unroll
        for (int p = 0; p < 4; p++) unpack2(acc3[i][p], dot[2*p], dot[2*p+1]);
        float best = INFINITY;
        int   bidx = 0x7fffffff;
#pragma unroll
        for (int j = 0; j < 8; j++) {
            int   idx = (j < 4) ? (cA0 + j) : (cB0 + j - 4);
            float cn  = (j < 4) ? cnA[j] : cnB[j - 4];
            // mimic reference rounding: (||z||^2 + ||c||^2) - 2*dot, fp32
            float d = (zsq[i] + cn) - 2.0f * dot[j];
            if (d < best || (d == best && idx < bidx)) { best = d; bidx = idx; }
        }
#pragma unroll
        for (int o = 16; o > 0; o >>= 1) {
            float ob = __shfl_xor_sync(0xffffffffu, best, o);
            int   oi = __shfl_xor_sync(0xffffffffu, bidx, o);
            if (ob < best || (ob == best && oi < bidx)) { best = ob; bidx = oi; }
        }
        int r = r0 + rb + i;
        if (lane == 0 && writeAux) outIdx[r] = (float)bidx;
        float4 cv = ((const float4*)cb)[bidx * 32 + lane];
        ((float4*)outZ)[(size_t)r * 32 + lane] = cv;
        float4 zv = ((float4*)sZ)[(rb + i) * 32 + lane];
        float d0 = cv.x - zv.x, d1 = cv.y - zv.y, d2 = cv.z - zv.z, d3 = cv.w - zv.w;
        lsum += (double)(d0 * d0 + d1 * d1 + d2 * d2 + d3 * d3);
    }

#pragma unroll
    for (int o = 16; o > 0; o >>= 1) lsum += __shfl_down_sync(0xffffffffu, lsum, o);
    if (lane == 0) sLoss[wid] = lsum;
    __syncthreads();

    // ---- per-block partial + last-block finalize ----
    if (!writeAux) return;
    __shared__ unsigned int sIsLast;
    if (tid == 0) {
        double t = 0.0;
#pragma unroll
        for (int w = 0; w < 8; w++) t += sLoss[w];
        g_partials[blockIdx.x] = t;
        __threadfence();
        unsigned int old = atomicAdd(&g_ticket, 1u);
        sIsLast = (old == (unsigned int)(gridDim.x - 1)) ? 1u : 0u;
    }
    __syncthreads();
    if (sIsLast) {
        __threadfence();
        double s = 0.0;
#pragma unroll
        for (int q = 0; q < NBLOCKS / NTHREADS; q++)
            s += g_partials[tid * (NBLOCKS / NTHREADS) + q];
#pragma unroll
        for (int o = 16; o > 0; o >>= 1) s += __shfl_down_sync(0xffffffffu, s, o);
        if (lane == 0) sLoss[wid] = s;
        __syncthreads();
        if (tid == 0) {
            double t = 0.0;
#pragma unroll
            for (int w = 0; w < 8; w++) t += sLoss[w];
            outLoss[0] = (float)(1.25 * t / (double)((long long)NROWS * DLAT));
            g_ticket = 0;
        }
    }
}

extern "C" void kernel_launch(void* const* d_in, const int* in_sizes, int n_in,
                              void* d_out, int out_size)
{
    const float* emb = (const float*)d_in[0];
    const float* W1  = (const float*)d_in[1];
    const float* b1  = (const float*)d_in[2];
    const float* g1  = (const float*)d_in[3];
    const float* be1 = (const float*)d_in[4];
    const float* W2  = (const float*)d_in[5];
    const float* b2  = (const float*)d_in[6];
    const float* g2  = (const float*)d_in[7];
    const float* be2 = (const float*)d_in[8];
    const float* cb  = (const float*)d_in[9];

    float* out     = (float*)d_out;
    float* outZ    = out;
    float* outLoss = out + (size_t)NROWS * DLAT;
    float* outIdx  = outLoss + 1;
    int writeAux = (out_size >= NROWS * DLAT + 1 + NROWS) ? 1 : 0;

    cudaFuncSetAttribute(vq_fused_kernel,
                         cudaFuncAttributeMaxDynamicSharedMemorySize, SMEM_BYTES);

    vq_fused_kernel<<<NBLOCKS, NTHREADS, SMEM_BYTES>>>(
        emb, W1, b1, g1, be1, W2, b2, g2, be2, cb, outZ, outIdx, outLoss, writeAux);
}

// round 6
// speedup vs baseline: 1.1131x; 1.1131x over previous
#include <cuda_runtime.h>
#include <math.h>

#define NROWS   131072          // 64*2048
#define DIN     384
#define DHID    256
#define DLAT    128
#define KC      256
#define TM      64
#define NTHREADS 256
#define NBLOCKS (NROWS / TM)    // 2048

// shared memory layout (floats):
//  [0,16384)      sH (64x256)  -- sZ (64x128) aliases [0,8192) after GEMM2
//  [16384,21504)  buf0: W tile (16x256=4096) + X tile (64x16=1024)
//  [21504,26624)  buf1: same            -- GEMM3 cb^T tile (32x260=8320) spans both buffers
//  [26624,26880)  sCn (256)
//  [26880,26896)  sLoss (8 doubles)
#define SW_BASE   16384
#define SW_BUFSZ  5120
#define SW_XOFF   4096
#define CN_BASE   26624
#define LOSS_BASE 26880
#define SMEM_FLOATS 26896
#define SMEM_BYTES  (SMEM_FLOATS * 4)

__device__ double       g_partials[NBLOCKS];
__device__ unsigned int g_ticket = 0;

typedef unsigned long long u64;

__device__ __forceinline__ float warp_sum(float v) {
#pragma unroll
    for (int o = 16; o > 0; o >>= 1) v += __shfl_xor_sync(0xffffffffu, v, o);
    return v;
}
__device__ __forceinline__ u64 dup2(float x) {
    u64 r; asm("mov.b64 %0, {%1, %1};" : "=l"(r) : "f"(x)); return r;
}
__device__ __forceinline__ u64 fma2(u64 a, u64 b, u64 c) {
    u64 d; asm("fma.rn.f32x2 %0, %1, %2, %3;" : "=l"(d) : "l"(a), "l"(b), "l"(c)); return d;
}
__device__ __forceinline__ void unpack2(u64 p, float& lo, float& hi) {
    asm("mov.b64 {%0, %1}, %2;" : "=f"(lo), "=f"(hi) : "l"(p));
}
__device__ __forceinline__ void cp16(unsigned dst, const void* src) {
    asm volatile("cp.async.cg.shared.global [%0], [%1], 16;" :: "r"(dst), "l"(src));
}
__device__ __forceinline__ void cp_commit() { asm volatile("cp.async.commit_group;"); }
__device__ __forceinline__ void cp_wait0()  { asm volatile("cp.async.wait_group 0;"); }

extern "C" __global__ void __launch_bounds__(NTHREADS, 2)
vq_fused_kernel(const float* __restrict__ emb,
                const float* __restrict__ W1, const float* __restrict__ b1,
                const float* __restrict__ g1, const float* __restrict__ be1,
                const float* __restrict__ W2, const float* __restrict__ b2,
                const float* __restrict__ g2, const float* __restrict__ be2,
                const float* __restrict__ cb,
                float* __restrict__ outZ,
                float* __restrict__ outIdx,
                float* __restrict__ outLoss,
                int writeAux)
{
    extern __shared__ float sm[];
    float*  sH   = sm;                       // 64x256
    float*  sZ   = sm;                       // 64x128, aliases sH after GEMM2
    float*  sCn  = sm + CN_BASE;
    double* sLoss = (double*)(sm + LOSS_BASE);

    const int tid  = threadIdx.x;
    const int wid  = tid >> 5;               // 0..7
    const int lane = tid & 31;
    const int rb   = wid * 8;                // this warp's 8 rows
    const int r0   = blockIdx.x * TM;
    const int cA0  = lane * 4;               // cols [4l, 4l+3]
    const int cB0  = 128 + lane * 4;         // cols [128+4l, ...]

    const unsigned swb[2] = { (unsigned)__cvta_generic_to_shared(sm + SW_BASE),
                              (unsigned)__cvta_generic_to_shared(sm + SW_BASE + SW_BUFSZ) };

    // X-tile staging: thread tid stages quad (tid&3) of row (tid>>2)
    const int xrow  = tid >> 2;
    const int xquad = tid & 3;
    const float* xsrc_row = emb + (size_t)(r0 + xrow) * DIN + xquad * 4;
    const unsigned xdst = (unsigned)((xrow * 16 + xquad * 4) * 4);   // byte offset in X region

    // prefetch tile 0 (W1 rows 0..15 + X cols 0..15)
    {
        const float4* src = (const float4*)W1;
#pragma unroll
        for (int q = 0; q < 4; q++) cp16(swb[0] + (tid + q * 256) * 16, src + tid + q * 256);
        cp16(swb[0] + SW_XOFF * 4 + xdst, xsrc_row);
        cp_commit();
    }

    // ---- codebook squared norms (one code per thread; overlaps tile-0 prefetch) ----
    {
        const float4* cv4 = (const float4*)cb + (size_t)tid * (DLAT / 4);
        float s = 0.f;
#pragma unroll
        for (int q = 0; q < 32; q++) {
            float4 v = cv4[q];
            s += v.x * v.x + v.y * v.y + v.z * v.z + v.w * v.w;
        }
        sCn[tid] = s;
    }

    // =================== GEMM1: [64,384] @ W1[384,256], k-tiles of 16, cp.async db ===================
    u64 acc1[8][4];
#pragma unroll
    for (int i = 0; i < 8; i++)
#pragma unroll
        for (int p = 0; p < 4; p++) acc1[i][p] = 0ULL;

    for (int t = 0; t < 24; t++) {
        cp_wait0();
        __syncthreads();
        if (t + 1 < 24) {
            const float4* src = (const float4*)(W1 + (t + 1) * 16 * 256);
            unsigned dst = swb[(t + 1) & 1];
#pragma unroll
            for (int q = 0; q < 4; q++) cp16(dst + (tid + q * 256) * 16, src + tid + q * 256);
            cp16(dst + SW_XOFF * 4 + xdst, xsrc_row + (t + 1) * 16);
            cp_commit();
        }
        const float* buf  = sm + SW_BASE + (t & 1) * SW_BUFSZ;
        const float* bufX = buf + SW_XOFF;
#pragma unroll
        for (int kg = 0; kg < 4; kg++) {
            ulonglong2 wA[4], wB[4];
#pragma unroll
            for (int kq = 0; kq < 4; kq++) {
                const int kk = kg * 4 + kq;
                wA[kq] = ((const ulonglong2*)buf)[kk * 64 + lane];
                wB[kq] = ((const ulonglong2*)buf)[kk * 64 + 32 + lane];
            }
#pragma unroll
            for (int i = 0; i < 8; i++) {
                float4 xv = *(const float4*)&bufX[(rb + i) * 16 + kg * 4];   // broadcast, 1 wf
#pragma unroll
                for (int kq = 0; kq < 4; kq++) {
                    float xs = (kq == 0) ? xv.x : (kq == 1) ? xv.y : (kq == 2) ? xv.z : xv.w;
                    u64 xx = dup2(xs);
                    acc1[i][0] = fma2(xx, wA[kq].x, acc1[i][0]);
                    acc1[i][1] = fma2(xx, wA[kq].y, acc1[i][1]);
                    acc1[i][2] = fma2(xx, wB[kq].x, acc1[i][2]);
                    acc1[i][3] = fma2(xx, wB[kq].y, acc1[i][3]);
                }
            }
        }
    }

    // prefetch W2 tile 0 (overlaps LN1+GELU); all warps past t=23 barrier -> buf0 free
    {
        const float4* src = (const float4*)W2;   // 16x128 = 512 float4; 2 per thread
#pragma unroll
        for (int q = 0; q < 2; q++) cp16(swb[0] + (tid + q * 256) * 16, src + tid + q * 256);
        cp_commit();
    }

    // =================== bias + LayerNorm1 + exact GELU -> sH ===================
    {
        float4 bA = __ldg((const float4*)(b1 + cA0)),  bB = __ldg((const float4*)(b1 + cB0));
        float4 gA = __ldg((const float4*)(g1 + cA0)),  gB = __ldg((const float4*)(g1 + cB0));
        float4 eA = __ldg((const float4*)(be1 + cA0)), eB = __ldg((const float4*)(be1 + cB0));
        float b1v[8] = {bA.x,bA.y,bA.z,bA.w,bB.x,bB.y,bB.z,bB.w};
        float g1v[8] = {gA.x,gA.y,gA.z,gA.w,gB.x,gB.y,gB.z,gB.w};
        float e1v[8] = {eA.x,eA.y,eA.z,eA.w,eB.x,eB.y,eB.z,eB.w};
#pragma unroll
        for (int i = 0; i < 8; i++) {
            float v[8], s = 0.f;
#pragma unroll
            for (int p = 0; p < 4; p++) unpack2(acc1[i][p], v[2*p], v[2*p+1]);
#pragma unroll
            for (int j = 0; j < 8; j++) { v[j] = v[j] + b1v[j]; s += v[j]; }
            s = warp_sum(s);
            float mean = s * (1.f / 256.f);
            float ss = 0.f;
#pragma unroll
            for (int j = 0; j < 8; j++) { float d = v[j] - mean; ss += d * d; }
            ss = warp_sum(ss);
            float rstd = rsqrtf(ss * (1.f / 256.f) + 1e-5f);
            float h[8];
#pragma unroll
            for (int j = 0; j < 8; j++) {
                float tt = (v[j] - mean) * rstd * g1v[j] + e1v[j];
                h[j] = 0.5f * tt * (1.f + erff(tt * 0.70710678118654752f));
            }
            *(float4*)&sH[(rb + i) * 256 + cA0] = make_float4(h[0], h[1], h[2], h[3]);
            *(float4*)&sH[(rb + i) * 256 + cB0] = make_float4(h[4], h[5], h[6], h[7]);
        }
    }
    __syncthreads();   // H visible to all warps

    // =================== GEMM2: [64,256] @ W2[256,128], k-tiles of 16, cp.async db ===================
    u64 acc2[8][2];
#pragma unroll
    for (int i = 0; i < 8; i++) { acc2[i][0] = 0ULL; acc2[i][1] = 0ULL; }

    for (int t = 0; t < 16; t++) {
        cp_wait0();
        __syncthreads();
        if (t + 1 < 16) {
            const float4* src = (const float4*)(W2 + (t + 1) * 16 * 128);
            unsigned dst = swb[(t + 1) & 1];
#pragma unroll
            for (int q = 0; q < 2; q++) cp16(dst + (tid + q * 256) * 16, src + tid + q * 256);
            cp_commit();
        }
        const float* buf = sm + SW_BASE + (t & 1) * SW_BUFSZ;
#pragma unroll
        for (int kg = 0; kg < 4; kg++) {
            ulonglong2 wv[4];
#pragma unroll
            for (int kq = 0; kq < 4; kq++)
                wv[kq] = ((const ulonglong2*)buf)[(kg * 4 + kq) * 32 + lane];
#pragma unroll
            for (int i = 0; i < 8; i++) {
                float4 xv = *(const float4*)&sH[(rb + i) * 256 + t * 16 + kg * 4];
#pragma unroll
                for (int kq = 0; kq < 4; kq++) {
                    float xs = (kq == 0) ? xv.x : (kq == 1) ? xv.y : (kq == 2) ? xv.z : xv.w;
                    u64 xx = dup2(xs);
                    acc2[i][0] = fma2(xx, wv[kq].x, acc2[i][0]);
                    acc2[i][1] = fma2(xx, wv[kq].y, acc2[i][1]);
                }
            }
        }
    }
    __syncthreads();   // all H reads done before z overwrites sH[0:8192)

    // =================== bias + LayerNorm2 -> z (SMEM, aliases sH), ||z||^2 ===================
    float zsq[8];
    {
        float4 b2v = __ldg((const float4*)(b2 + cA0));
        float4 g2v = __ldg((const float4*)(g2 + cA0));
        float4 e2v = __ldg((const float4*)(be2 + cA0));
#pragma unroll
        for (int i = 0; i < 8; i++) {
            float a0, a1, a2, a3;
            unpack2(acc2[i][0], a0, a1);
            unpack2(acc2[i][1], a2, a3);
            float v0 = a0 + b2v.x, v1 = a1 + b2v.y;
            float v2 = a2 + b2v.z, v3 = a3 + b2v.w;
            float s = warp_sum(v0 + v1 + v2 + v3);
            float mean = s * (1.f / 128.f);
            float d0 = v0 - mean, d1 = v1 - mean, d2 = v2 - mean, d3 = v3 - mean;
            float ss = warp_sum(d0 * d0 + d1 * d1 + d2 * d2 + d3 * d3);
            float rstd = rsqrtf(ss * (1.f / 128.f) + 1e-5f);
            float z0 = d0 * rstd * g2v.x + e2v.x;
            float z1 = d1 * rstd * g2v.y + e2v.y;
            float z2 = d2 * rstd * g2v.z + e2v.z;
            float z3 = d3 * rstd * g2v.w + e2v.w;
            zsq[i] = warp_sum(z0 * z0 + z1 * z1 + z2 * z2 + z3 * z3);
            *(float4*)&sZ[(rb + i) * 128 + cA0] = make_float4(z0, z1, z2, z3);
        }
    }
    __syncthreads();   // z visible

    // =================== distance GEMM: z[64,128] . cb[256,128]^T, k-tiles of 32 ===================
    u64 acc3[8][4];
#pragma unroll
    for (int i = 0; i < 8; i++)
#pragma unroll
        for (int p = 0; p < 4; p++) acc3[i][p] = 0ULL;

    float* sWc = sm + SW_BASE;   // 32x260 transposed cb tile (spans both buffers)

    for (int kt = 0; kt < DLAT; kt += 32) {
        // stage transposed codebook tile: sWc[kk*260 + code] = cb[code][kt+kk]
        {
            const float4* cv4 = (const float4*)cb + (size_t)tid * 32 + (kt >> 2);
#pragma unroll
            for (int q = 0; q < 8; q++) {
                float4 v = cv4[q];
                int kk = q * 4;
                sWc[(kk + 0) * 260 + tid] = v.x;
                sWc[(kk + 1) * 260 + tid] = v.y;
                sWc[(kk + 2) * 260 + tid] = v.z;
                sWc[(kk + 3) * 260 + tid] = v.w;
            }
        }
        __syncthreads();
#pragma unroll
        for (int kg = 0; kg < 8; kg++) {
            ulonglong2 cA[2], cB[2];   // 2 kq at a time to bound regs
#pragma unroll
            for (int kh = 0; kh < 2; kh++) {
#pragma unroll
                for (int kq = 0; kq < 2; kq++) {
                    const int kk = kg * 4 + kh * 2 + kq;
                    cA[kq] = *(const ulonglong2*)&sWc[kk * 260 + cA0];
                    cB[kq] = *(const ulonglong2*)&sWc[kk * 260 + cB0];
                }
#pragma unroll
                for (int i = 0; i < 8; i++) {
                    float2 zp = *(const float2*)&sZ[(rb + i) * 128 + kt + kg * 4 + kh * 2];
#pragma unroll
                    for (int kq = 0; kq < 2; kq++) {
                        u64 zz = dup2(kq == 0 ? zp.x : zp.y);
                        acc3[i][0] = fma2(zz, cA[kq].x, acc3[i][0]);
                        acc3[i][1] = fma2(zz, cA[kq].y, acc3[i][1]);
                        acc3[i][2] = fma2(zz, cB[kq].x, acc3[i][2]);
                        acc3[i][3] = fma2(zz, cB[kq].y, acc3[i][3]);
                    }
                }
            }
        }
        __syncthreads();   // before next tile's STS overwrite
    }

    // ---- codebook norms for this thread's 8 codes ----
    float cnA[4], cnB[4];
#pragma unroll
    for (int q = 0; q < 4; q++) { cnA[q] = sCn[cA0 + q]; cnB[q] = sCn[cB0 + q]; }

    // =================== argmin + outputs + loss ===================
    double lsum = 0.0;
#pragma unroll
    for (int i = 0; i < 8; i++) {
        float dot[8];
#pragma unroll
        for (int p = 0; p < 4; p++) unpack2(acc3[i][p], dot[2*p], dot[2*p+1]);
        float best = INFINITY;
        int   bidx = 0x7fffffff;
#pragma unroll
        for (int j = 0; j < 8; j++) {
            int   idx = (j < 4) ? (cA0 + j) : (cB0 + j - 4);
            float cn  = (j < 4) ? cnA[j] : cnB[j - 4];
            // mimic reference rounding: (||z||^2 + ||c||^2) - 2*dot, fp32
            float d = (zsq[i] + cn) - 2.0f * dot[j];
            if (d < best || (d == best && idx < bidx)) { best = d; bidx = idx; }
        }
#pragma unroll
        for (int o = 16; o > 0; o >>= 1) {
            float ob = __shfl_xor_sync(0xffffffffu, best, o);
            int   oi = __shfl_xor_sync(0xffffffffu, bidx, o);
            if (ob < best || (ob == best && oi < bidx)) { best = ob; bidx = oi; }
        }
        int r = r0 + rb + i;
        if (lane == 0 && writeAux) outIdx[r] = (float)bidx;
        float4 cv = ((const float4*)cb)[bidx * 32 + lane];
        ((float4*)outZ)[(size_t)r * 32 + lane] = cv;
        float4 zv = ((float4*)sZ)[(rb + i) * 32 + lane];
        float d0 = cv.x - zv.x, d1 = cv.y - zv.y, d2 = cv.z - zv.z, d3 = cv.w - zv.w;
        lsum += (double)(d0 * d0 + d1 * d1 + d2 * d2 + d3 * d3);
    }

#pragma unroll
    for (int o = 16; o > 0; o >>= 1) lsum += __shfl_down_sync(0xffffffffu, lsum, o);
    if (lane == 0) sLoss[wid] = lsum;
    __syncthreads();

    // ---- per-block partial + last-block finalize ----
    if (!writeAux) return;
    __shared__ unsigned int sIsLast;
    if (tid == 0) {
        double t = 0.0;
#pragma unroll
        for (int w = 0; w < 8; w++) t += sLoss[w];
        g_partials[blockIdx.x] = t;
        __threadfence();
        unsigned int old = atomicAdd(&g_ticket, 1u);
        sIsLast = (old == (unsigned int)(gridDim.x - 1)) ? 1u : 0u;
    }
    __syncthreads();
    if (sIsLast) {
        __threadfence();
        double s = 0.0;
#pragma unroll
        for (int q = 0; q < NBLOCKS / NTHREADS; q++)
            s += g_partials[tid * (NBLOCKS / NTHREADS) + q];
#pragma unroll
        for (int o = 16; o > 0; o >>= 1) s += __shfl_down_sync(0xffffffffu, s, o);
        if (lane == 0) sLoss[wid] = s;
        __syncthreads();
        if (tid == 0) {
            double t = 0.0;
#pragma unroll
            for (int w = 0; w < 8; w++) t += sLoss[w];
            outLoss[0] = (float)(1.25 * t / (double)((long long)NROWS * DLAT));
            g_ticket = 0;
        }
    }
}

extern "C" void kernel_launch(void* const* d_in, const int* in_sizes, int n_in,
                              void* d_out, int out_size)
{
    const float* emb = (const float*)d_in[0];
    const float* W1  = (const float*)d_in[1];
    const float* b1  = (const float*)d_in[2];
    const float* g1  = (const float*)d_in[3];
    const float* be1 = (const float*)d_in[4];
    const float* W2  = (const float*)d_in[5];
    const float* b2  = (const float*)d_in[6];
    const float* g2  = (const float*)d_in[7];
    const float* be2 = (const float*)d_in[8];
    const float* cb  = (const float*)d_in[9];

    float* out     = (float*)d_out;
    float* outZ    = out;
    float* outLoss = out + (size_t)NROWS * DLAT;
    float* outIdx  = outLoss + 1;
    int writeAux = (out_size >= NROWS * DLAT + 1 + NROWS) ? 1 : 0;

    cudaFuncSetAttribute(vq_fused_kernel,
                         cudaFuncAttributeMaxDynamicSharedMemorySize, SMEM_BYTES);

    vq_fused_kernel<<<NBLOCKS, NTHREADS, SMEM_BYTES>>>(
        emb, W1, b1, g1, be1, W2, b2, g2, be2, cb, outZ, outIdx, outLoss, writeAux);
}